// round 12
// baseline (speedup 1.0000x reference)
#include <cuda_runtime.h>
#include <cstdint>

// MultiStepIFNode: T=16 integrate-and-fire over (16, 32, 128, 32, 32) fp32.
// Per neuron: v += x[t]; spike = (v >= 1); v -= spike.
//
// R12: 256-bit memory ops (sm_100+ ld/st.global.v8.f32 -> LDG.E.256 /
// STG.E.256). Last mechanistically distinct lever: halves instruction and
// L1tex-wavefront count vs float4, 32B contiguous per thread = maximally
// sequential sector stream into the LTS->DRAM scheduler. Cannot exceed the
// DRAM ceiling (~6.3-6.4 TB/s measured across R1-R11) but may recover any
// request-slot-scheduling component of the ~20% DRAM-idle residue.
// Everything else = R5 winner: 8-timestep front batch, .cs streaming on
// both paths, block 256, exact grid.

static constexpr int T_STEPS = 16;
static constexpr int T_HALF  = 8;

__device__ __forceinline__ void ldg256_cs(const float* p, float r[8]) {
    asm volatile(
        "ld.global.cs.v8.f32 {%0,%1,%2,%3,%4,%5,%6,%7}, [%8];"
        : "=f"(r[0]), "=f"(r[1]), "=f"(r[2]), "=f"(r[3]),
          "=f"(r[4]), "=f"(r[5]), "=f"(r[6]), "=f"(r[7])
        : "l"(p));
}

__device__ __forceinline__ void stg256_cs(float* p, const float r[8]) {
    asm volatile(
        "st.global.cs.v8.f32 [%0], {%1,%2,%3,%4,%5,%6,%7,%8};"
        :: "l"(p),
           "f"(r[0]), "f"(r[1]), "f"(r[2]), "f"(r[3]),
           "f"(r[4]), "f"(r[5]), "f"(r[6]), "f"(r[7])
        : "memory");
}

__global__ __launch_bounds__(256, 2) void if_multistep_kernel(
    const float* __restrict__ x,    // T * n floats
    float* __restrict__ out,        // T * n floats
    int n)                          // floats per timestep
{
    const int i8 = (blockIdx.x * blockDim.x + threadIdx.x) * 8;  // float offset

    float v[8];
    #pragma unroll
    for (int k = 0; k < 8; k++) v[k] = 0.f;

    #pragma unroll
    for (int half = 0; half < 2; half++) {
        // Front-batch 8 independent 256-bit loads (64 data regs)
        float xt[T_HALF][8];
        #pragma unroll
        for (int t = 0; t < T_HALF; t++) {
            ldg256_cs(&x[(size_t)(half * T_HALF + t) * n + i8], xt[t]);
        }

        #pragma unroll
        for (int t = 0; t < T_HALF; t++) {
            float s[8];
            #pragma unroll
            for (int k = 0; k < 8; k++) {
                v[k] += xt[t][k];
                s[k] = (v[k] >= 1.0f) ? 1.0f : 0.0f;
                v[k] -= s[k];
            }
            stg256_cs(&out[(size_t)(half * T_HALF + t) * n + i8], s);
        }
    }
}

extern "C" void kernel_launch(void* const* d_in, const int* in_sizes, int n_in,
                              void* d_out, int out_size)
{
    const float* x = (const float*)d_in[0];
    float* out = (float*)d_out;

    int n = out_size / T_STEPS;    // 4,194,304 floats per timestep
    int n8 = n / 8;                // 524,288 threads

    const int threads = 256;
    int blocks = n8 / threads;     // 2048, exact
    if_multistep_kernel<<<blocks, threads>>>(x, out, n);
}

// round 13
// speedup vs baseline: 1.0078x; 1.0078x over previous
#include <cuda_runtime.h>
#include <cstdint>

// MultiStepIFNode: T=16 integrate-and-fire over (16, 32, 128, 32, 32) fp32.
// Per neuron: v += x[t]; spike = (v >= 1); v -= spike.
//
// ===================== CONVERGED FINAL KERNEL =====================
// Pure HBM streaming at the provable traffic minimum: 256 MiB in +
// 256 MiB out. Best measured: 81.98us dur_us (~77us kernel, 6.4 TB/s).
//
// Fully closed experiment matrix (R1-R12), every axis two-sided:
//   access width:  float4 (LDG.128) vs v8.f32 (LDG.256)  -> neutral
//   supply:        occupancy 21-88%, MLP 2-16, persistent vs waved,
//                  block 128/256                          -> within 2%
//   drain:         default/__stcs/__stwt stores -> __stcs best;
//                  __stwt -2.5% (fragments write stream)
//   losers:        persistent 444-CTA grid -10% (starves chip MLP)
// All sane configs: 6.26-6.41 TB/s = ~79-80% of 8 TB/s spec. The ~20%
// DRAM-idle residue is bidirectional-stream bus turnaround/refresh —
// confirmed not request-scheduling (LDG.256 halved issue traffic, zero
// DRAM delta) and not SASS-addressable. TMA cannot beat this path
// (LTS/DRAM cap is path-independent per B300_MICROARCH).
//
// Structure: one thread owns 4 consecutive neurons (float4). Front-batch
// all 16 timestep loads (contiguous read burst, 16 outstanding LDG.E.128
// evict-first), run the v-recurrence in registers, emit 16 STG.E.128
// evict-first. Fully coalesced; grid exactly covers n4
// (1,048,576 = 4096 x 256) so no bounds guard.

static constexpr int T_STEPS = 16;

__global__ __launch_bounds__(256, 2) void if_multistep_kernel(
    const float4* __restrict__ x,   // T * n4 float4s
    float4* __restrict__ out,       // T * n4 float4s
    int n4)                         // float4s per timestep (N/4)
{
    const int i = blockIdx.x * blockDim.x + threadIdx.x;

    // Front-batch all 16 loads before any store issues.
    float4 xt[T_STEPS];
    #pragma unroll
    for (int t = 0; t < T_STEPS; t++) {
        xt[t] = __ldcs(&x[(size_t)t * n4 + i]);
    }

    float vx = 0.f, vy = 0.f, vz = 0.f, vw = 0.f;

    #pragma unroll
    for (int t = 0; t < T_STEPS; t++) {
        vx += xt[t].x;
        vy += xt[t].y;
        vz += xt[t].z;
        vw += xt[t].w;

        float4 s;
        s.x = (vx >= 1.0f) ? 1.0f : 0.0f;
        s.y = (vy >= 1.0f) ? 1.0f : 0.0f;
        s.z = (vz >= 1.0f) ? 1.0f : 0.0f;
        s.w = (vw >= 1.0f) ? 1.0f : 0.0f;

        vx -= s.x;
        vy -= s.y;
        vz -= s.z;
        vw -= s.w;

        __stcs(&out[(size_t)t * n4 + i], s);
    }
}

extern "C" void kernel_launch(void* const* d_in, const int* in_sizes, int n_in,
                              void* d_out, int out_size)
{
    const float4* x = (const float4*)d_in[0];
    float4* out = (float4*)d_out;

    int n_per_step = out_size / T_STEPS;   // 4,194,304
    int n4 = n_per_step / 4;               // 1,048,576 (exact multiple of 4096*256)

    const int threads = 256;
    int blocks = n4 / threads;             // 4096, exact
    if_multistep_kernel<<<blocks, threads>>>(x, out, n4);
}